// round 4
// baseline (speedup 1.0000x reference)
#include <cuda_runtime.h>
#include <cuda_bf16.h>
#include <cstdint>

// ---------------------------------------------------------------------------
// NeuralODE persistent kernel, round 4:
//  - ldmatrix.x4 A-fragment loads (4x fewer shared-pipe issues)
//  - double-buffered h activations (h2 overlays dead W2 smem) -> 3 barriers/step
//  - tanh.approx.bf16x2 epilogues (half the MUFU work)
//  - W2/W3 B-fragments + biases register-resident (from round 3)
// ---------------------------------------------------------------------------

namespace {

constexpr int B_    = 4096;
constexpr int S_    = 64;
constexpr int H_    = 256;
constexpr int MROWS = 32;              // rows per CTA
constexpr int CTAS  = B_ / MROWS;      // 128
constexpr int NTH   = 256;             // 8 warps

// u32 strides (stride % 8 == 4 -> conflict-free ldmatrix phases)
constexpr int HSTR = 132;
constexpr int XSTR = 36;

// smem layout (bytes)
constexpr int SM_W1P0 = 0;                           // 16384
constexpr int SM_W1P1 = SM_W1P0 + 16384;             // 16384
constexpr int SM_W2P0 = SM_W1P1 + 16384;             // 65536 (dead after init)
constexpr int SM_W2P1 = SM_W2P0 + 65536;             // 65536 (dead after init)
constexpr int SM_W3P0 = SM_W2P1 + 65536;             // 16384 (dead after init)
constexpr int SM_W3P1 = SM_W3P0 + 16384;             // 16384 (dead after init)
constexpr int SM_H    = SM_W3P1 + 16384;             // 16896 (h1)
constexpr int SM_XB   = SM_H + MROWS * HSTR * 4;     // 4608
constexpr int SM_H2   = SM_W2P0;                     // h2 overlays dead W2 plane
constexpr int SMEM_BYTES = SM_XB + MROWS * XSTR * 4 + 256;

__device__ __forceinline__ uint32_t pack_bf16(float lo, float hi) {
    __nv_bfloat162 v = __floats2bfloat162_rn(lo, hi);
    return *reinterpret_cast<uint32_t*>(&v);
}

__device__ __forceinline__ uint32_t tanh_bf16x2(uint32_t v) {
    uint32_t r;
    asm("tanh.approx.bf16x2 %0, %1;" : "=r"(r) : "r"(v));
    return r;
}

__device__ __forceinline__ void ldsm_x4(uint32_t& r0, uint32_t& r1,
                                        uint32_t& r2, uint32_t& r3,
                                        uint32_t addr) {
    asm volatile("ldmatrix.sync.aligned.m8n8.x4.shared.b16 {%0,%1,%2,%3}, [%4];"
                 : "=r"(r0), "=r"(r1), "=r"(r2), "=r"(r3) : "r"(addr));
}

__device__ __forceinline__ void mma16816(float* d,
                                         uint32_t a0, uint32_t a1, uint32_t a2, uint32_t a3,
                                         uint32_t b0, uint32_t b1) {
    asm volatile(
        "mma.sync.aligned.m16n8k16.row.col.f32.bf16.bf16.f32 "
        "{%0,%1,%2,%3},{%4,%5,%6,%7},{%8,%9},{%0,%1,%2,%3};\n"
        : "+f"(d[0]), "+f"(d[1]), "+f"(d[2]), "+f"(d[3])
        : "r"(a0), "r"(a1), "r"(a2), "r"(a3), "r"(b0), "r"(b1));
}

// Shuffle fp32 W[K][N] (row-major) into one bf16x2 B-fragment plane.
//   idx = ((nt*NKB + kb)*4 + t)*8 + g ; n = nt*8+g ; k0 = kb*16 + t*2 + koff
template <int NKB, int LOG2NKB>
__device__ void fill_plane(uint32_t* plane, const float* __restrict__ W,
                           int N, int koff, int tid) {
    const int total = N * NKB * 4;
    for (int e = tid; e < total; e += NTH) {
        int gg   = e & 7;
        int tt   = (e >> 3) & 3;
        int kbnt = e >> 5;
        int kb   = kbnt & (NKB - 1);
        int nt   = kbnt >> LOG2NKB;
        int n    = nt * 8 + gg;
        int k0   = kb * 16 + tt * 2 + koff;
        plane[e] = pack_bf16(W[k0 * N + n], W[(k0 + 1) * N + n]);
    }
}

} // namespace

extern "C" __global__ void __launch_bounds__(NTH, 1)
neuralode_persistent_kernel(const float* __restrict__ x0,
                            const float* __restrict__ W1, const float* __restrict__ b1,
                            const float* __restrict__ W2, const float* __restrict__ b2,
                            const float* __restrict__ W3, const float* __restrict__ b3,
                            const float* __restrict__ dt_scale,
                            const int*   __restrict__ num_steps,
                            float* __restrict__ out)
{
    extern __shared__ unsigned char smem_raw[];
    uint32_t* w1p0 = reinterpret_cast<uint32_t*>(smem_raw + SM_W1P0);
    uint32_t* w1p1 = reinterpret_cast<uint32_t*>(smem_raw + SM_W1P1);
    uint32_t* w2p0 = reinterpret_cast<uint32_t*>(smem_raw + SM_W2P0);
    uint32_t* w2p1 = reinterpret_cast<uint32_t*>(smem_raw + SM_W2P1);
    uint32_t* w3p0 = reinterpret_cast<uint32_t*>(smem_raw + SM_W3P0);
    uint32_t* w3p1 = reinterpret_cast<uint32_t*>(smem_raw + SM_W3P1);
    uint32_t* hbuf = reinterpret_cast<uint32_t*>(smem_raw + SM_H);
    uint32_t* h2buf= reinterpret_cast<uint32_t*>(smem_raw + SM_H2);
    uint32_t* xb   = reinterpret_cast<uint32_t*>(smem_raw + SM_XB);

    const int tid = threadIdx.x;

    // ---- one-time weight shuffle into fragment-ordered smem planes ----
    fill_plane<4, 2>(w1p0, W1, H_, 0, tid);
    fill_plane<4, 2>(w1p1, W1, H_, 8, tid);
    fill_plane<16, 4>(w2p0, W2, H_, 0, tid);
    fill_plane<16, 4>(w2p1, W2, H_, 8, tid);
    fill_plane<16, 4>(w3p0, W3, S_, 0, tid);
    fill_plane<16, 4>(w3p1, W3, S_, 8, tid);

    const int   nsteps  = num_steps[0];
    const float dts     = dt_scale[0] * 0.01f;
    const int   row0    = blockIdx.x * MROWS;
    const long  ostride = (long)(nsteps + 1) * S_;

    // ---- t=0: trajectory[., 0, .] = x0 ----
    for (int i = tid; i < MROWS * S_; i += NTH) {
        int r = i >> 6, c = i & 63;
        out[(long)(row0 + r) * ostride + c] = x0[(row0 + r) * S_ + c];
    }

    // ---- warp/lane decomposition: 8 warps, each 4 n-groups x 2 m-tiles ----
    const int warp = tid >> 5, lane = tid & 31;
    const int g = lane >> 2, t = lane & 3;
    const int ng  = warp;              // 0..7 column group
    const int tg  = t * 8 + g;

    // ldmatrix lane-address mapping: quad q -> (row-half, k-half)
    const int q     = lane >> 3;
    const int rrow  = (lane & 7) | ((q & 1) << 3);   // 0..15
    const int koffu = (q >> 1) << 2;                 // 0 or 4 u32

    const uint32_t sbase = (uint32_t)__cvta_generic_to_shared(smem_raw);
    uint32_t h1a[2], h2a[2], xba[2];
#pragma unroll
    for (int mt = 0; mt < 2; ++mt) {
        h1a[mt] = sbase + SM_H  + ((mt * 16 + rrow) * HSTR + koffu) * 4;
        h2a[mt] = sbase + SM_H2 + ((mt * 16 + rrow) * HSTR + koffu) * 4;
        xba[mt] = sbase + SM_XB + ((mt * 16 + rrow) * XSTR + koffu) * 4;
    }

    __syncthreads();   // planes ready

    // ---- register-resident weight fragments (constant over all steps) ----
    uint32_t wb2a[4][16], wb2b[4][16];
#pragma unroll
    for (int j = 0; j < 4; ++j)
#pragma unroll
        for (int kb = 0; kb < 16; ++kb) {
            int idx = ((ng * 4 + j) * 16 + kb) * 32 + tg;
            wb2a[j][kb] = w2p0[idx];
            wb2b[j][kb] = w2p1[idx];
        }
    uint32_t wb3a[16], wb3b[16];
#pragma unroll
    for (int kb = 0; kb < 16; ++kb) {
        int idx = (ng * 16 + kb) * 32 + tg;
        wb3a[kb] = w3p0[idx];
        wb3b[kb] = w3p1[idx];
    }

    // ---- register-resident biases (fragment layout) ----
    float pb1[4][2], pb2[4][2], pb3[2];
#pragma unroll
    for (int j = 0; j < 4; ++j) {
        int c = (ng * 4 + j) * 8 + t * 2;
        pb1[j][0] = b1[c];     pb1[j][1] = b1[c + 1];
        pb2[j][0] = b2[c];     pb2[j][1] = b2[c + 1];
    }
    {
        int c = ng * 8 + t * 2;
        pb3[0] = b3[c]; pb3[1] = b3[c + 1];
    }

    // ---- x state in registers (GEMM3-fragment layout, both m-tiles) ----
    float xr[2][4];
#pragma unroll
    for (int mt = 0; mt < 2; ++mt) {
        int r = mt * 16 + g;
        int colb = ng * 8 + t * 2;
        const float* p = x0 + (long)(row0 + r) * S_ + colb;
        xr[mt][0] = p[0];
        xr[mt][1] = p[1];
        xr[mt][2] = p[8 * S_];
        xr[mt][3] = p[8 * S_ + 1];
        int pidx = ng * 4 + t;
        xb[r * XSTR + pidx]       = pack_bf16(xr[mt][0], xr[mt][1]);
        xb[(r + 8) * XSTR + pidx] = pack_bf16(xr[mt][2], xr[mt][3]);
    }
    // NOTE: this barrier also guarantees all weight-plane register reads are
    // done before h2buf (overlaying W2 plane) is first written in step 0.
    __syncthreads();

    // ======================= main time-step loop ==========================
    for (int step = 0; step < nsteps; ++step) {
        float acc[2][4][4];

        // ---- GEMM1: [32,64] @ W1[64,256] (B frags from smem, A via LDSM) ----
#pragma unroll
        for (int mt = 0; mt < 2; ++mt)
#pragma unroll
            for (int j = 0; j < 4; ++j)
#pragma unroll
                for (int q2 = 0; q2 < 4; ++q2) acc[mt][j][q2] = 0.f;

#pragma unroll
        for (int kb = 0; kb < 4; ++kb) {
            uint32_t a[2][4];
#pragma unroll
            for (int mt = 0; mt < 2; ++mt)
                ldsm_x4(a[mt][0], a[mt][1], a[mt][2], a[mt][3],
                        xba[mt] + kb * 32);
#pragma unroll
            for (int j = 0; j < 4; ++j) {
                int idx = ((ng * 4 + j) * 4 + kb) * 32 + tg;
                uint32_t b0 = w1p0[idx], b1f = w1p1[idx];
#pragma unroll
                for (int mt = 0; mt < 2; ++mt)
                    mma16816(acc[mt][j], a[mt][0], a[mt][1], a[mt][2], a[mt][3],
                             b0, b1f);
            }
        }
        // epilogue1: h1 = tanh(acc + b1)
#pragma unroll
        for (int mt = 0; mt < 2; ++mt)
#pragma unroll
            for (int j = 0; j < 4; ++j) {
                int pidx = (ng * 4 + j) * 4 + t;
                int r = mt * 16 + g;
                hbuf[r * HSTR + pidx] =
                    tanh_bf16x2(pack_bf16(acc[mt][j][0] + pb1[j][0],
                                          acc[mt][j][1] + pb1[j][1]));
                hbuf[(r + 8) * HSTR + pidx] =
                    tanh_bf16x2(pack_bf16(acc[mt][j][2] + pb1[j][0],
                                          acc[mt][j][3] + pb1[j][1]));
            }
        __syncthreads();   // bar A: h1 complete

        // ---- GEMM2: [32,256] @ W2[256,256] (B in regs, A via LDSM) ----
#pragma unroll
        for (int mt = 0; mt < 2; ++mt)
#pragma unroll
            for (int j = 0; j < 4; ++j)
#pragma unroll
                for (int q2 = 0; q2 < 4; ++q2) acc[mt][j][q2] = 0.f;

#pragma unroll 4
        for (int kb = 0; kb < 16; ++kb) {
            uint32_t a[2][4];
#pragma unroll
            for (int mt = 0; mt < 2; ++mt)
                ldsm_x4(a[mt][0], a[mt][1], a[mt][2], a[mt][3],
                        h1a[mt] + kb * 32);
#pragma unroll
            for (int j = 0; j < 4; ++j)
#pragma unroll
                for (int mt = 0; mt < 2; ++mt)
                    mma16816(acc[mt][j], a[mt][0], a[mt][1], a[mt][2], a[mt][3],
                             wb2a[j][kb], wb2b[j][kb]);
        }

        // epilogue2: h2 = tanh(acc + b2)  (distinct buffer -> no barrier first)
#pragma unroll
        for (int mt = 0; mt < 2; ++mt)
#pragma unroll
            for (int j = 0; j < 4; ++j) {
                int pidx = (ng * 4 + j) * 4 + t;
                int r = mt * 16 + g;
                h2buf[r * HSTR + pidx] =
                    tanh_bf16x2(pack_bf16(acc[mt][j][0] + pb2[j][0],
                                          acc[mt][j][1] + pb2[j][1]));
                h2buf[(r + 8) * HSTR + pidx] =
                    tanh_bf16x2(pack_bf16(acc[mt][j][2] + pb2[j][0],
                                          acc[mt][j][3] + pb2[j][1]));
            }
        __syncthreads();   // bar B: h2 complete

        // ---- GEMM3: [32,256] @ W3[256,64] (B in regs, A via LDSM) ----
        float acc3[2][4];
#pragma unroll
        for (int mt = 0; mt < 2; ++mt)
#pragma unroll
            for (int q2 = 0; q2 < 4; ++q2) acc3[mt][q2] = 0.f;

#pragma unroll 4
        for (int kb = 0; kb < 16; ++kb) {
#pragma unroll
            for (int mt = 0; mt < 2; ++mt) {
                uint32_t a0, a1v, a2, a3;
                ldsm_x4(a0, a1v, a2, a3, h2a[mt] + kb * 32);
                mma16816(acc3[mt], a0, a1v, a2, a3, wb3a[kb], wb3b[kb]);
            }
        }

        // epilogue3: x += (acc3 + b3) * dts ; trajectory store + xb refresh
#pragma unroll
        for (int mt = 0; mt < 2; ++mt) {
            int r = mt * 16 + g;
            int colb = ng * 8 + t * 2;
            xr[mt][0] += (acc3[mt][0] + pb3[0]) * dts;
            xr[mt][1] += (acc3[mt][1] + pb3[1]) * dts;
            xr[mt][2] += (acc3[mt][2] + pb3[0]) * dts;
            xr[mt][3] += (acc3[mt][3] + pb3[1]) * dts;
            float* orow = out + (long)(row0 + r) * ostride
                        + (long)(step + 1) * S_ + colb;
            __stcs(reinterpret_cast<float2*>(orow),
                   make_float2(xr[mt][0], xr[mt][1]));
            __stcs(reinterpret_cast<float2*>(orow + 8 * ostride),
                   make_float2(xr[mt][2], xr[mt][3]));
            int pidx = ng * 4 + t;
            xb[r * XSTR + pidx]       = pack_bf16(xr[mt][0], xr[mt][1]);
            xb[(r + 8) * XSTR + pidx] = pack_bf16(xr[mt][2], xr[mt][3]);
        }
        __syncthreads();   // bar C: xb complete for next step
    }
}

extern "C" void kernel_launch(void* const* d_in, const int* in_sizes, int n_in,
                              void* d_out, int out_size)
{
    (void)in_sizes; (void)n_in; (void)out_size;
    const float* x0       = (const float*)d_in[0];
    const float* W1       = (const float*)d_in[1];
    const float* b1       = (const float*)d_in[2];
    const float* W2       = (const float*)d_in[3];
    const float* b2       = (const float*)d_in[4];
    const float* W3       = (const float*)d_in[5];
    const float* b3       = (const float*)d_in[6];
    const float* dt_scale = (const float*)d_in[7];
    const int*   nsteps   = (const int*)d_in[8];
    float*       out      = (float*)d_out;

    cudaFuncSetAttribute(neuralode_persistent_kernel,
                         cudaFuncAttributeMaxDynamicSharedMemorySize, SMEM_BYTES);
    neuralode_persistent_kernel<<<CTAS, NTH, SMEM_BYTES>>>(
        x0, W1, b1, W2, b2, W3, b3, dt_scale, nsteps, out);
}

// round 5
// speedup vs baseline: 1.5120x; 1.5120x over previous
#include <cuda_runtime.h>
#include <cuda_bf16.h>
#include <cstdint>

// ---------------------------------------------------------------------------
// NeuralODE persistent kernel, round 5:
//  Round-4 structure with the spill bug fixed: EVERY loop indexing a register
//  array is fully unrolled (partial unroll made wb2a/wb3a dynamically indexed
//  -> ptxas spilled 160 regs to local memory -> L2 at 19.8%, 855us).
//  - ldmatrix.x4 A-fragment loads
//  - double-buffered h (h2 overlays dead W2 smem) -> 3 barriers/step
//  - tanh.approx.bf16x2 epilogues
//  - W2/W3 B-fragments + biases register-resident
// ---------------------------------------------------------------------------

namespace {

constexpr int B_    = 4096;
constexpr int S_    = 64;
constexpr int H_    = 256;
constexpr int MROWS = 32;              // rows per CTA
constexpr int CTAS  = B_ / MROWS;      // 128
constexpr int NTH   = 256;             // 8 warps

// u32 strides (stride % 8 == 4 -> conflict-free ldmatrix phases)
constexpr int HSTR = 132;
constexpr int XSTR = 36;

// smem layout (bytes)
constexpr int SM_W1P0 = 0;                           // 16384
constexpr int SM_W1P1 = SM_W1P0 + 16384;             // 16384
constexpr int SM_W2P0 = SM_W1P1 + 16384;             // 65536 (dead after init)
constexpr int SM_W2P1 = SM_W2P0 + 65536;             // 65536 (dead after init)
constexpr int SM_W3P0 = SM_W2P1 + 65536;             // 16384 (dead after init)
constexpr int SM_W3P1 = SM_W3P0 + 16384;             // 16384 (dead after init)
constexpr int SM_H    = SM_W3P1 + 16384;             // 16896 (h1)
constexpr int SM_XB   = SM_H + MROWS * HSTR * 4;     // 4608
constexpr int SM_H2   = SM_W2P0;                     // h2 overlays dead W2 plane
constexpr int SMEM_BYTES = SM_XB + MROWS * XSTR * 4 + 256;

__device__ __forceinline__ uint32_t pack_bf16(float lo, float hi) {
    __nv_bfloat162 v = __floats2bfloat162_rn(lo, hi);
    return *reinterpret_cast<uint32_t*>(&v);
}

__device__ __forceinline__ uint32_t tanh_bf16x2(uint32_t v) {
    uint32_t r;
    asm("tanh.approx.bf16x2 %0, %1;" : "=r"(r) : "r"(v));
    return r;
}

__device__ __forceinline__ void ldsm_x4(uint32_t& r0, uint32_t& r1,
                                        uint32_t& r2, uint32_t& r3,
                                        uint32_t addr) {
    asm volatile("ldmatrix.sync.aligned.m8n8.x4.shared.b16 {%0,%1,%2,%3}, [%4];"
                 : "=r"(r0), "=r"(r1), "=r"(r2), "=r"(r3) : "r"(addr));
}

__device__ __forceinline__ void mma16816(float* d,
                                         uint32_t a0, uint32_t a1, uint32_t a2, uint32_t a3,
                                         uint32_t b0, uint32_t b1) {
    asm volatile(
        "mma.sync.aligned.m16n8k16.row.col.f32.bf16.bf16.f32 "
        "{%0,%1,%2,%3},{%4,%5,%6,%7},{%8,%9},{%0,%1,%2,%3};\n"
        : "+f"(d[0]), "+f"(d[1]), "+f"(d[2]), "+f"(d[3])
        : "r"(a0), "r"(a1), "r"(a2), "r"(a3), "r"(b0), "r"(b1));
}

// Shuffle fp32 W[K][N] (row-major) into one bf16x2 B-fragment plane.
//   idx = ((nt*NKB + kb)*4 + t)*8 + g ; n = nt*8+g ; k0 = kb*16 + t*2 + koff
template <int NKB, int LOG2NKB>
__device__ void fill_plane(uint32_t* plane, const float* __restrict__ W,
                           int N, int koff, int tid) {
    const int total = N * NKB * 4;
    for (int e = tid; e < total; e += NTH) {
        int gg   = e & 7;
        int tt   = (e >> 3) & 3;
        int kbnt = e >> 5;
        int kb   = kbnt & (NKB - 1);
        int nt   = kbnt >> LOG2NKB;
        int n    = nt * 8 + gg;
        int k0   = kb * 16 + tt * 2 + koff;
        plane[e] = pack_bf16(W[k0 * N + n], W[(k0 + 1) * N + n]);
    }
}

} // namespace

extern "C" __global__ void __launch_bounds__(NTH, 1)
neuralode_persistent_kernel(const float* __restrict__ x0,
                            const float* __restrict__ W1, const float* __restrict__ b1,
                            const float* __restrict__ W2, const float* __restrict__ b2,
                            const float* __restrict__ W3, const float* __restrict__ b3,
                            const float* __restrict__ dt_scale,
                            const int*   __restrict__ num_steps,
                            float* __restrict__ out)
{
    extern __shared__ unsigned char smem_raw[];
    uint32_t* w1p0 = reinterpret_cast<uint32_t*>(smem_raw + SM_W1P0);
    uint32_t* w1p1 = reinterpret_cast<uint32_t*>(smem_raw + SM_W1P1);
    uint32_t* w2p0 = reinterpret_cast<uint32_t*>(smem_raw + SM_W2P0);
    uint32_t* w2p1 = reinterpret_cast<uint32_t*>(smem_raw + SM_W2P1);
    uint32_t* w3p0 = reinterpret_cast<uint32_t*>(smem_raw + SM_W3P0);
    uint32_t* w3p1 = reinterpret_cast<uint32_t*>(smem_raw + SM_W3P1);
    uint32_t* hbuf = reinterpret_cast<uint32_t*>(smem_raw + SM_H);
    uint32_t* h2buf= reinterpret_cast<uint32_t*>(smem_raw + SM_H2);
    uint32_t* xb   = reinterpret_cast<uint32_t*>(smem_raw + SM_XB);

    const int tid = threadIdx.x;

    // ---- one-time weight shuffle into fragment-ordered smem planes ----
    fill_plane<4, 2>(w1p0, W1, H_, 0, tid);
    fill_plane<4, 2>(w1p1, W1, H_, 8, tid);
    fill_plane<16, 4>(w2p0, W2, H_, 0, tid);
    fill_plane<16, 4>(w2p1, W2, H_, 8, tid);
    fill_plane<16, 4>(w3p0, W3, S_, 0, tid);
    fill_plane<16, 4>(w3p1, W3, S_, 8, tid);

    const int   nsteps  = num_steps[0];
    const float dts     = dt_scale[0] * 0.01f;
    const int   row0    = blockIdx.x * MROWS;
    const long  ostride = (long)(nsteps + 1) * S_;

    // ---- t=0: trajectory[., 0, .] = x0 ----
    for (int i = tid; i < MROWS * S_; i += NTH) {
        int r = i >> 6, c = i & 63;
        out[(long)(row0 + r) * ostride + c] = x0[(row0 + r) * S_ + c];
    }

    // ---- warp/lane decomposition: 8 warps, each 4 n-groups x 2 m-tiles ----
    const int warp = tid >> 5, lane = tid & 31;
    const int g = lane >> 2, t = lane & 3;
    const int ng  = warp;              // 0..7 column group
    const int tg  = t * 8 + g;

    // ldmatrix lane-address mapping: quad q -> (row-half, k-half)
    const int q     = lane >> 3;
    const int rrow  = (lane & 7) | ((q & 1) << 3);   // 0..15
    const int koffu = (q >> 1) << 2;                 // 0 or 4 u32

    const uint32_t sbase = (uint32_t)__cvta_generic_to_shared(smem_raw);
    uint32_t h1a[2], h2a[2], xba[2];
#pragma unroll
    for (int mt = 0; mt < 2; ++mt) {
        h1a[mt] = sbase + SM_H  + ((mt * 16 + rrow) * HSTR + koffu) * 4;
        h2a[mt] = sbase + SM_H2 + ((mt * 16 + rrow) * HSTR + koffu) * 4;
        xba[mt] = sbase + SM_XB + ((mt * 16 + rrow) * XSTR + koffu) * 4;
    }

    __syncthreads();   // planes ready

    // ---- register-resident weight fragments (constant over all steps) ----
    uint32_t wb2a[4][16], wb2b[4][16];
#pragma unroll
    for (int j = 0; j < 4; ++j)
#pragma unroll
        for (int kb = 0; kb < 16; ++kb) {
            int idx = ((ng * 4 + j) * 16 + kb) * 32 + tg;
            wb2a[j][kb] = w2p0[idx];
            wb2b[j][kb] = w2p1[idx];
        }
    uint32_t wb3a[16], wb3b[16];
#pragma unroll
    for (int kb = 0; kb < 16; ++kb) {
        int idx = (ng * 16 + kb) * 32 + tg;
        wb3a[kb] = w3p0[idx];
        wb3b[kb] = w3p1[idx];
    }

    // ---- register-resident biases (fragment layout) ----
    float pb1[4][2], pb2[4][2], pb3[2];
#pragma unroll
    for (int j = 0; j < 4; ++j) {
        int c = (ng * 4 + j) * 8 + t * 2;
        pb1[j][0] = b1[c];     pb1[j][1] = b1[c + 1];
        pb2[j][0] = b2[c];     pb2[j][1] = b2[c + 1];
    }
    {
        int c = ng * 8 + t * 2;
        pb3[0] = b3[c]; pb3[1] = b3[c + 1];
    }

    // ---- x state in registers (GEMM3-fragment layout, both m-tiles) ----
    float xr[2][4];
#pragma unroll
    for (int mt = 0; mt < 2; ++mt) {
        int r = mt * 16 + g;
        int colb = ng * 8 + t * 2;
        const float* p = x0 + (long)(row0 + r) * S_ + colb;
        xr[mt][0] = p[0];
        xr[mt][1] = p[1];
        xr[mt][2] = p[8 * S_];
        xr[mt][3] = p[8 * S_ + 1];
        int pidx = ng * 4 + t;
        xb[r * XSTR + pidx]       = pack_bf16(xr[mt][0], xr[mt][1]);
        xb[(r + 8) * XSTR + pidx] = pack_bf16(xr[mt][2], xr[mt][3]);
    }
    // Also guarantees weight-plane register reads complete before h2buf
    // (overlaying the W2 plane) is first written in step 0.
    __syncthreads();

    // ======================= main time-step loop ==========================
    for (int step = 0; step < nsteps; ++step) {
        float acc[2][4][4];

        // ---- GEMM1: [32,64] @ W1[64,256] (B from smem, A via LDSM) ----
#pragma unroll
        for (int mt = 0; mt < 2; ++mt)
#pragma unroll
            for (int j = 0; j < 4; ++j)
#pragma unroll
                for (int q2 = 0; q2 < 4; ++q2) acc[mt][j][q2] = 0.f;

#pragma unroll
        for (int kb = 0; kb < 4; ++kb) {
            uint32_t a[2][4];
#pragma unroll
            for (int mt = 0; mt < 2; ++mt)
                ldsm_x4(a[mt][0], a[mt][1], a[mt][2], a[mt][3],
                        xba[mt] + kb * 32);
#pragma unroll
            for (int j = 0; j < 4; ++j) {
                int idx = ((ng * 4 + j) * 4 + kb) * 32 + tg;
                uint32_t b0 = w1p0[idx], b1f = w1p1[idx];
#pragma unroll
                for (int mt = 0; mt < 2; ++mt)
                    mma16816(acc[mt][j], a[mt][0], a[mt][1], a[mt][2], a[mt][3],
                             b0, b1f);
            }
        }
        // epilogue1: h1 = tanh(acc + b1)
#pragma unroll
        for (int mt = 0; mt < 2; ++mt)
#pragma unroll
            for (int j = 0; j < 4; ++j) {
                int pidx = (ng * 4 + j) * 4 + t;
                int r = mt * 16 + g;
                hbuf[r * HSTR + pidx] =
                    tanh_bf16x2(pack_bf16(acc[mt][j][0] + pb1[j][0],
                                          acc[mt][j][1] + pb1[j][1]));
                hbuf[(r + 8) * HSTR + pidx] =
                    tanh_bf16x2(pack_bf16(acc[mt][j][2] + pb1[j][0],
                                          acc[mt][j][3] + pb1[j][1]));
            }
        __syncthreads();   // bar A: h1 complete

        // ---- GEMM2: [32,256] @ W2[256,256] (B in regs, A via LDSM) ----
        // k-loop MUST be fully unrolled: wb2a/wb2b indexed by kb.
#pragma unroll
        for (int mt = 0; mt < 2; ++mt)
#pragma unroll
            for (int j = 0; j < 4; ++j)
#pragma unroll
                for (int q2 = 0; q2 < 4; ++q2) acc[mt][j][q2] = 0.f;

#pragma unroll
        for (int kb = 0; kb < 16; ++kb) {
            uint32_t a[2][4];
#pragma unroll
            for (int mt = 0; mt < 2; ++mt)
                ldsm_x4(a[mt][0], a[mt][1], a[mt][2], a[mt][3],
                        h1a[mt] + kb * 32);
#pragma unroll
            for (int j = 0; j < 4; ++j)
#pragma unroll
                for (int mt = 0; mt < 2; ++mt)
                    mma16816(acc[mt][j], a[mt][0], a[mt][1], a[mt][2], a[mt][3],
                             wb2a[j][kb], wb2b[j][kb]);
        }

        // epilogue2: h2 = tanh(acc + b2) (distinct buffer -> no barrier first)
#pragma unroll
        for (int mt = 0; mt < 2; ++mt)
#pragma unroll
            for (int j = 0; j < 4; ++j) {
                int pidx = (ng * 4 + j) * 4 + t;
                int r = mt * 16 + g;
                h2buf[r * HSTR + pidx] =
                    tanh_bf16x2(pack_bf16(acc[mt][j][0] + pb2[j][0],
                                          acc[mt][j][1] + pb2[j][1]));
                h2buf[(r + 8) * HSTR + pidx] =
                    tanh_bf16x2(pack_bf16(acc[mt][j][2] + pb2[j][0],
                                          acc[mt][j][3] + pb2[j][1]));
            }
        __syncthreads();   // bar B: h2 complete

        // ---- GEMM3: [32,256] @ W3[256,64] (B in regs, A via LDSM) ----
        // k-loop fully unrolled: wb3a/wb3b indexed by kb.
        float acc3[2][4];
#pragma unroll
        for (int mt = 0; mt < 2; ++mt)
#pragma unroll
            for (int q2 = 0; q2 < 4; ++q2) acc3[mt][q2] = 0.f;

#pragma unroll
        for (int kb = 0; kb < 16; ++kb) {
#pragma unroll
            for (int mt = 0; mt < 2; ++mt) {
                uint32_t a0, a1v, a2, a3;
                ldsm_x4(a0, a1v, a2, a3, h2a[mt] + kb * 32);
                mma16816(acc3[mt], a0, a1v, a2, a3, wb3a[kb], wb3b[kb]);
            }
        }

        // epilogue3: x += (acc3 + b3) * dts ; trajectory store + xb refresh
#pragma unroll
        for (int mt = 0; mt < 2; ++mt) {
            int r = mt * 16 + g;
            int colb = ng * 8 + t * 2;
            xr[mt][0] += (acc3[mt][0] + pb3[0]) * dts;
            xr[mt][1] += (acc3[mt][1] + pb3[1]) * dts;
            xr[mt][2] += (acc3[mt][2] + pb3[0]) * dts;
            xr[mt][3] += (acc3[mt][3] + pb3[1]) * dts;
            float* orow = out + (long)(row0 + r) * ostride
                        + (long)(step + 1) * S_ + colb;
            __stcs(reinterpret_cast<float2*>(orow),
                   make_float2(xr[mt][0], xr[mt][1]));
            __stcs(reinterpret_cast<float2*>(orow + 8 * ostride),
                   make_float2(xr[mt][2], xr[mt][3]));
            int pidx = ng * 4 + t;
            xb[r * XSTR + pidx]       = pack_bf16(xr[mt][0], xr[mt][1]);
            xb[(r + 8) * XSTR + pidx] = pack_bf16(xr[mt][2], xr[mt][3]);
        }
        __syncthreads();   // bar C: xb complete for next step
    }
}

extern "C" void kernel_launch(void* const* d_in, const int* in_sizes, int n_in,
                              void* d_out, int out_size)
{
    (void)in_sizes; (void)n_in; (void)out_size;
    const float* x0       = (const float*)d_in[0];
    const float* W1       = (const float*)d_in[1];
    const float* b1       = (const float*)d_in[2];
    const float* W2       = (const float*)d_in[3];
    const float* b2       = (const float*)d_in[4];
    const float* W3       = (const float*)d_in[5];
    const float* b3       = (const float*)d_in[6];
    const float* dt_scale = (const float*)d_in[7];
    const int*   nsteps   = (const int*)d_in[8];
    float*       out      = (float*)d_out;

    cudaFuncSetAttribute(neuralode_persistent_kernel,
                         cudaFuncAttributeMaxDynamicSharedMemorySize, SMEM_BYTES);
    neuralode_persistent_kernel<<<CTAS, NTH, SMEM_BYTES>>>(
        x0, W1, b1, W2, b2, W3, b3, dt_scale, nsteps, out);
}